// round 7
// baseline (speedup 1.0000x reference)
#include <cuda_runtime.h>
#include <cstdint>
#include <cstddef>

// ---------------- problem constants ----------------
#define B_     2
#define N_     2048
#define DIMX   256
#define NC     3
#define NH     8
#define DHD    64
#define DI     512      /* NH*DHD */
#define FF     192      /* DHD*NC */
#define MTOT   4096     /* B_*N_ */
#define OALL   1536     /* 3*DI  */
#define BHCNT  16       /* B_*NH */
#define SCALE_F 0.07216878364870322f   /* (NC*DHD)^-0.5 = 192^-0.5 */
#define NEG_BIG (-3.4028235e38f)

// ---------------- scratch (device globals; no cudaMalloc allowed) ----------------
__device__ float g_xt[NC * DIMX * MTOT];       // [c][i][bn]         12.6 MB
__device__ float g_wt_all[DIMX * OALL];        // [i][o] o: q(512)|k(512)|v(512)
__device__ float g_wt_out[DI * DIMX];          // [i][o]
__device__ float g_Qt[BHCNT * FF * N_];        // [bh][f][n]         25.2 MB
__device__ float g_Kt[BHCNT * FF * N_];        // [bh][f][n]
__device__ float g_Vn[BHCNT * N_ * FF];        // [bh][n][f]
__device__ float g_ksq[BHCNT * N_];            // [bh][n]
__device__ float g_Oct[NC * DI * MTOT];        // [c][i][bn]         25.2 MB
__device__ unsigned char g_mask[MTOT];         // canonical byte mask

// ---------------- 0) canonicalize mask (dtype-robust) ----------------
// Harness stores the jax bool mask as int32 (confirmed: rel_err signature of
// reading int32 ones as bytes). Detect byte-vs-word encoding from word 0 and
// normalize to one byte per (b,n).
__global__ void k_mask_prep(const void* __restrict__ mask_raw) {
    const uint32_t w0 = *(const uint32_t*)mask_raw;
    // all-true uint8 mask -> 0x01010101 ; int32/float32 -> one element per word
    const bool bytes_mode = ((w0 & 0xFFFFFF00u) != 0u) && (w0 != 0x3F800000u)
                            ? true : false;
    const int n = blockIdx.x * 256 + threadIdx.x;
    if (n >= MTOT) return;
    unsigned char v;
    if (bytes_mode) {
        v = ((const unsigned char*)mask_raw)[n] != 0;
    } else {
        v = ((const uint32_t*)mask_raw)[n] != 0u;   // int32(0/1) or float32 bits
    }
    g_mask[n] = v;
}

// ---------------- 1) transpose x: x[bn][i][c] -> xt[c][i][bn] ----------------
__global__ void k_transpose_x(const float* __restrict__ x) {
    __shared__ float s[NC][32][33];
    const int i0 = blockIdx.x * 32;
    const int m0 = blockIdx.y * 32;
    const int tx = threadIdx.x, ty = threadIdx.y;
    const int ir = i0 + tx, mr = m0 + ty;
    #pragma unroll
    for (int c = 0; c < NC; c++)
        s[c][ty][tx] = x[(size_t)mr * (DIMX * NC) + ir * NC + c];
    __syncthreads();
    const int iw = i0 + ty, mw = m0 + tx;
    #pragma unroll
    for (int c = 0; c < NC; c++)
        g_xt[(size_t)c * DIMX * MTOT + (size_t)iw * MTOT + mw] = s[c][tx][ty];
}

// ---------------- 2) transpose weights ----------------
__global__ void k_transpose_w(const float* __restrict__ wq,
                              const float* __restrict__ wkv,
                              const float* __restrict__ wout) {
    const int idx = blockIdx.x * 256 + threadIdx.x;
    if (idx < DIMX * OALL) {
        const int i = idx / OALL, o = idx % OALL;
        g_wt_all[idx] = (o < DI) ? wq[(size_t)o * DIMX + i]
                                 : wkv[(size_t)(o - DI) * DIMX + i];
    }
    if (idx < DI * DIMX) {
        const int i = idx / DIMX, o = idx % DIMX;
        g_wt_out[idx] = wout[(size_t)o * DI + i];
    }
}

// ---------------- 3) QKV projection SGEMM ----------------
// C[m][o] = sum_i xt[c][i][m] * wt_all[i][o], scatter epilogue to Qt/Kt/Vn.
__global__ void k_gemm_proj() {
    __shared__ float As[32][64];
    __shared__ float Bs[32][64];
    const int c  = blockIdx.z;
    const int m0 = blockIdx.x * 64;
    const int o0 = blockIdx.y * 64;
    const float* A = g_xt + (size_t)c * DIMX * MTOT;
    const int t = threadIdx.x;
    const int tm = t & 15, tn = t >> 4;

    float acc[4][4];
    #pragma unroll
    for (int a = 0; a < 4; a++)
        #pragma unroll
        for (int bq = 0; bq < 4; bq++) acc[a][bq] = 0.f;

    for (int k0 = 0; k0 < DIMX; k0 += 32) {
        #pragma unroll
        for (int j = 0; j < 2; j++) {
            const int p = t + j * 256;
            const int kk = p >> 4, x4 = (p & 15) << 2;
            *(float4*)&As[kk][x4] = *(const float4*)&A[(size_t)(k0 + kk) * MTOT + m0 + x4];
            *(float4*)&Bs[kk][x4] = *(const float4*)&g_wt_all[(size_t)(k0 + kk) * OALL + o0 + x4];
        }
        __syncthreads();
        #pragma unroll
        for (int k = 0; k < 32; k++) {
            float ra[4];
            #pragma unroll
            for (int im = 0; im < 4; im++) ra[im] = As[k][tm + im * 16];
            const float4 rb = *(float4*)&Bs[k][tn << 2];
            #pragma unroll
            for (int im = 0; im < 4; im++) {
                acc[im][0] = fmaf(ra[im], rb.x, acc[im][0]);
                acc[im][1] = fmaf(ra[im], rb.y, acc[im][1]);
                acc[im][2] = fmaf(ra[im], rb.z, acc[im][2]);
                acc[im][3] = fmaf(ra[im], rb.w, acc[im][3]);
            }
        }
        __syncthreads();
    }

    #pragma unroll
    for (int im = 0; im < 4; im++) {
        const int m = m0 + tm + im * 16;
        const int b = m >> 11, n = m & 2047;
        #pragma unroll
        for (int io = 0; io < 4; io++) {
            const int o = o0 + (tn << 2) + io;
            const float v = acc[im][io];
            if (o < 2 * DI) {
                const int oo = o & 511;
                const int h = oo >> 6, d = oo & 63;
                float* dst = (o < DI) ? g_Qt : g_Kt;
                dst[((size_t)(b * NH + h) * FF + c * DHD + d) * N_ + n] = v;
            } else {
                const int oo = o - 2 * DI;
                const int h = oo >> 6, d = oo & 63;
                g_Vn[((size_t)(b * NH + h) * N_ + n) * FF + c * DHD + d] = v;
            }
        }
    }
}

// ---------------- 4) k_sq ----------------
__global__ void k_ksq() {
    const int bh = blockIdx.y;
    const int n  = blockIdx.x * 256 + threadIdx.x;
    const float* kp = g_Kt + (size_t)bh * FF * N_ + n;
    float s = 0.f;
    #pragma unroll 4
    for (int f = 0; f < FF; f++) {
        const float v = kp[(size_t)f * N_];
        s = fmaf(v, v, s);
    }
    g_ksq[bh * N_ + n] = s;
}

// ---------------- 5) attention ----------------
// block = (q-tile of 64, bh). 8 warps, each owns 8 query rows entirely.
__global__ void __launch_bounds__(256, 1) k_attn() {
    extern __shared__ float sm[];
    float* sQ = sm;                    // [192][64]
    float* sK = sQ + FF * 64;          // [192][64]
    float* sV = sK + FF * 64;          // [64][192]
    float* sP = sV + 64 * FF;          // [8 warps][8 qi][64 kj]
    float* sB = sP + 8 * 8 * 64;       // [64] per-key bias (masked -ksq)

    const int bh = blockIdx.y;
    const int q0 = blockIdx.x * 64;
    const int b  = bh >> 3;
    const int h  = bh & 7;
    const int t  = threadIdx.x;
    const int w  = t >> 5, l = t & 31;
    const int qb = w * 8;

    const float* Qg = g_Qt + (size_t)bh * FF * N_;
    const float* Kg = g_Kt + (size_t)bh * FF * N_;
    const float* Vg = g_Vn + (size_t)bh * N_ * FF;
    const float* kqg = g_ksq + bh * N_;
    const unsigned char* mg = g_mask + b * N_;

    // load Q tile [f][qi]
    #pragma unroll
    for (int j = 0; j < 12; j++) {
        const int p = t + j * 256;
        const int f = p >> 4, x4 = (p & 15) << 2;
        *(float4*)&sQ[f * 64 + x4] = *(const float4*)&Qg[(size_t)f * N_ + q0 + x4];
    }

    float m_r[8], l_r[8], oacc[8][6];
    #pragma unroll
    for (int i = 0; i < 8; i++) {
        m_r[i] = NEG_BIG; l_r[i] = 0.f;
        #pragma unroll
        for (int mm = 0; mm < 6; mm++) oacc[i][mm] = 0.f;
    }

    float* pw = sP + w * 512;

    for (int kt = 0; kt < N_; kt += 64) {
        __syncthreads();
        #pragma unroll
        for (int j = 0; j < 12; j++) {
            const int p = t + j * 256;
            const int f = p >> 4, x4 = (p & 15) << 2;
            *(float4*)&sK[f * 64 + x4] = *(const float4*)&Kg[(size_t)f * N_ + kt + x4];
        }
        #pragma unroll
        for (int j = 0; j < 12; j++) {
            const int p = t + j * 256;
            const int r = p / 48, f4 = (p % 48) << 2;
            *(float4*)&sV[r * FF + f4] = *(const float4*)&Vg[(size_t)(kt + r) * FF + f4];
        }
        if (t < 64) {
            const int jj = kt + t;
            sB[t] = mg[jj] ? -kqg[jj] : NEG_BIG;
        }
        __syncthreads();

        // ---- S = Q . K^T (warp: 8 qi x 64 kj; lane: 8 qi x 2 kj) ----
        float s0[8], s1[8];
        #pragma unroll
        for (int i = 0; i < 8; i++) { s0[i] = 0.f; s1[i] = 0.f; }
        #pragma unroll 4
        for (int f = 0; f < FF; f++) {
            const float4 qa = *(float4*)&sQ[f * 64 + qb];
            const float4 qc = *(float4*)&sQ[f * 64 + qb + 4];
            const float2 kk = *(float2*)&sK[f * 64 + 2 * l];
            float qv[8];
            qv[0] = qa.x; qv[1] = qa.y; qv[2] = qa.z; qv[3] = qa.w;
            qv[4] = qc.x; qv[5] = qc.y; qv[6] = qc.z; qv[7] = qc.w;
            #pragma unroll
            for (int i = 0; i < 8; i++) {
                s0[i] = fmaf(qv[i], kk.x, s0[i]);
                s1[i] = fmaf(qv[i], kk.y, s1[i]);
            }
        }

        // logits: (2*qk - ksq)*SCALE; (q_sq is row-constant => softmax-invariant)
        const float bb0 = sB[2 * l], bb1 = sB[2 * l + 1];
        #pragma unroll
        for (int i = 0; i < 8; i++) {
            s0[i] = (2.f * s0[i] + bb0) * SCALE_F;
            s1[i] = (2.f * s1[i] + bb1) * SCALE_F;
        }

        // row max across warp
        float mt[8];
        #pragma unroll
        for (int i = 0; i < 8; i++) mt[i] = fmaxf(s0[i], s1[i]);
        #pragma unroll
        for (int off = 16; off; off >>= 1)
            #pragma unroll
            for (int i = 0; i < 8; i++)
                mt[i] = fmaxf(mt[i], __shfl_xor_sync(0xffffffffu, mt[i], off));

        // online softmax update
        float rs[8];
        #pragma unroll
        for (int i = 0; i < 8; i++) {
            const float mn = fmaxf(m_r[i], mt[i]);
            const float al = __expf(m_r[i] - mn);
            m_r[i] = mn;
            s0[i] = __expf(s0[i] - mn);
            s1[i] = __expf(s1[i] - mn);
            rs[i] = s0[i] + s1[i];
            l_r[i] *= al;
            #pragma unroll
            for (int mm = 0; mm < 6; mm++) oacc[i][mm] *= al;
        }
        #pragma unroll
        for (int off = 16; off; off >>= 1)
            #pragma unroll
            for (int i = 0; i < 8; i++)
                rs[i] += __shfl_xor_sync(0xffffffffu, rs[i], off);
        #pragma unroll
        for (int i = 0; i < 8; i++) l_r[i] += rs[i];

        // stash P (warp-private region)
        #pragma unroll
        for (int i = 0; i < 8; i++) {
            float2 pp; pp.x = s0[i]; pp.y = s1[i];
            *(float2*)&pw[i * 64 + 2 * l] = pp;
        }
        __syncwarp();

        // ---- O += P . V (lane owns f = l + 32*mm) ----
        #pragma unroll 2
        for (int kj = 0; kj < 64; kj++) {
            float vv[6];
            #pragma unroll
            for (int mm = 0; mm < 6; mm++) vv[mm] = sV[kj * FF + l + 32 * mm];
            #pragma unroll
            for (int i = 0; i < 8; i++) {
                const float p = pw[i * 64 + kj];
                #pragma unroll
                for (int mm = 0; mm < 6; mm++)
                    oacc[i][mm] = fmaf(p, vv[mm], oacc[i][mm]);
            }
        }
        __syncwarp();
    }

    // epilogue: write O transposed [c][i=h*64+d][bn]
    #pragma unroll
    for (int i = 0; i < 8; i++) {
        const float inv = 1.f / l_r[i];
        const int mrow = b * N_ + q0 + qb + i;
        #pragma unroll
        for (int mm = 0; mm < 6; mm++) {
            const int f = l + 32 * mm;
            const int cc = f >> 6, d = f & 63;
            g_Oct[(size_t)cc * DI * MTOT + (size_t)(h * DHD + d) * MTOT + mrow] =
                oacc[i][mm] * inv;
        }
    }
}

// ---------------- 6) output projection SGEMM ----------------
__global__ void k_gemm_out(float* __restrict__ out) {
    __shared__ float As[32][64];
    __shared__ float Bs[32][64];
    const int c  = blockIdx.z;
    const int m0 = blockIdx.x * 64;
    const int o0 = blockIdx.y * 64;
    const float* A = g_Oct + (size_t)c * DI * MTOT;
    const int t = threadIdx.x;
    const int tm = t & 15, tn = t >> 4;

    float acc[4][4];
    #pragma unroll
    for (int a = 0; a < 4; a++)
        #pragma unroll
        for (int bq = 0; bq < 4; bq++) acc[a][bq] = 0.f;

    for (int k0 = 0; k0 < DI; k0 += 32) {
        #pragma unroll
        for (int j = 0; j < 2; j++) {
            const int p = t + j * 256;
            const int kk = p >> 4, x4 = (p & 15) << 2;
            *(float4*)&As[kk][x4] = *(const float4*)&A[(size_t)(k0 + kk) * MTOT + m0 + x4];
            *(float4*)&Bs[kk][x4] = *(const float4*)&g_wt_out[(size_t)(k0 + kk) * DIMX + o0 + x4];
        }
        __syncthreads();
        #pragma unroll
        for (int k = 0; k < 32; k++) {
            float ra[4];
            #pragma unroll
            for (int im = 0; im < 4; im++) ra[im] = As[k][tm + im * 16];
            const float4 rb = *(float4*)&Bs[k][tn << 2];
            #pragma unroll
            for (int im = 0; im < 4; im++) {
                acc[im][0] = fmaf(ra[im], rb.x, acc[im][0]);
                acc[im][1] = fmaf(ra[im], rb.y, acc[im][1]);
                acc[im][2] = fmaf(ra[im], rb.z, acc[im][2]);
                acc[im][3] = fmaf(ra[im], rb.w, acc[im][3]);
            }
        }
        __syncthreads();
    }

    #pragma unroll
    for (int im = 0; im < 4; im++) {
        const int m = m0 + tm + im * 16;
        #pragma unroll
        for (int io = 0; io < 4; io++) {
            const int o = o0 + (tn << 2) + io;
            out[(size_t)m * (DIMX * NC) + o * NC + c] = acc[im][io];
        }
    }
}

// ---------------- launch ----------------
extern "C" void kernel_launch(void* const* d_in, const int* in_sizes, int n_in,
                              void* d_out, int out_size) {
    (void)in_sizes; (void)n_in; (void)out_size;
    const float* x    = (const float*)d_in[0];
    const void*  mask = d_in[1];
    const float* wq   = (const float*)d_in[2];
    const float* wkv  = (const float*)d_in[3];
    const float* wout = (const float*)d_in[4];
    float* out = (float*)d_out;

    const size_t ATTN_SMEM =
        (size_t)(FF * 64 * 2 + 64 * FF + 8 * 8 * 64 + 64) * sizeof(float); // 164096 B
    cudaFuncSetAttribute(k_attn, cudaFuncAttributeMaxDynamicSharedMemorySize,
                         (int)ATTN_SMEM);

    k_mask_prep<<<dim3((MTOT + 255) / 256), 256>>>(mask);
    k_transpose_x<<<dim3(DIMX / 32, MTOT / 32), dim3(32, 32)>>>(x);
    k_transpose_w<<<dim3((DIMX * OALL + 255) / 256), 256>>>(wq, wkv, wout);
    k_gemm_proj<<<dim3(MTOT / 64, OALL / 64, NC), 256>>>();
    k_ksq<<<dim3(N_ / 256, BHCNT), 256>>>();
    k_attn<<<dim3(N_ / 64, BHCNT), 256, ATTN_SMEM>>>();
    k_gemm_out<<<dim3(MTOT / 64, DIMX / 64, NC), 256>>>(out);
}

// round 8
// speedup vs baseline: 1.0929x; 1.0929x over previous
#include <cuda_runtime.h>
#include <cstdint>
#include <cstddef>

// ---------------- problem constants ----------------
#define B_     2
#define N_     2048
#define DIMX   256
#define NC     3
#define NH     8
#define DHD    64
#define DI     512      /* NH*DHD */
#define FF     192      /* DHD*NC */
#define MTOT   4096     /* B_*N_ */
#define OALL   1536     /* 3*DI  */
#define BHCNT  16       /* B_*NH */
#define KSPLIT 2
#define KRANGE (N_ / KSPLIT)
#define SCALE_F 0.07216878364870322f   /* (NC*DHD)^-0.5 */
#define NEG_BIG (-3.4028235e38f)

typedef unsigned long long u64;

// ---------------- packed f32x2 helpers (sm_103a FFMA2) ----------------
__device__ __forceinline__ u64 pk2(float x) {
    u64 d; unsigned int xi = __float_as_uint(x);
    asm("mov.b64 %0, {%1, %1};" : "=l"(d) : "r"(xi));
    return d;
}
__device__ __forceinline__ void fma2(u64 &d, u64 a, u64 b) {
    asm("fma.rn.f32x2 %0, %1, %2, %0;" : "+l"(d) : "l"(a), "l"(b));
}
__device__ __forceinline__ u64 mul2(u64 a, u64 b) {
    u64 d; asm("mul.rn.f32x2 %0, %1, %2;" : "=l"(d) : "l"(a), "l"(b));
    return d;
}
__device__ __forceinline__ float2 up2(u64 d) {
    unsigned int lo, hi;
    asm("mov.b64 {%0, %1}, %2;" : "=r"(lo), "=r"(hi) : "l"(d));
    return make_float2(__uint_as_float(lo), __uint_as_float(hi));
}

// ---------------- scratch ----------------
__device__ float g_xt[NC * DIMX * MTOT];
__device__ float g_wt_all[DIMX * OALL];
__device__ float g_wt_out[DI * DIMX];
__device__ float g_Qt[BHCNT * FF * N_];
__device__ float g_Kt[BHCNT * FF * N_];
__device__ float g_Vn[BHCNT * N_ * FF];
__device__ float g_ksq[BHCNT * N_];
__device__ float g_Oct[NC * DI * MTOT];
__device__ float g_pO[KSPLIT * BHCNT * N_ * FF];   // partial O (unnormalized)
__device__ float g_pm[KSPLIT * BHCNT * N_];
__device__ float g_pl[KSPLIT * BHCNT * N_];
__device__ unsigned char g_mask[MTOT];

// ---------------- 0) mask canonicalize ----------------
__global__ void k_mask_prep(const void* __restrict__ mask_raw) {
    const uint32_t w0 = *(const uint32_t*)mask_raw;
    const bool bytes_mode = ((w0 & 0xFFFFFF00u) != 0u) && (w0 != 0x3F800000u);
    const int n = blockIdx.x * 256 + threadIdx.x;
    if (n >= MTOT) return;
    unsigned char v;
    if (bytes_mode) v = ((const unsigned char*)mask_raw)[n] != 0;
    else            v = ((const uint32_t*)mask_raw)[n] != 0u;
    g_mask[n] = v;
}

// ---------------- 1) transpose x ----------------
__global__ void k_transpose_x(const float* __restrict__ x) {
    __shared__ float s[NC][32][33];
    const int i0 = blockIdx.x * 32;
    const int m0 = blockIdx.y * 32;
    const int tx = threadIdx.x, ty = threadIdx.y;
    const int ir = i0 + tx, mr = m0 + ty;
    #pragma unroll
    for (int c = 0; c < NC; c++)
        s[c][ty][tx] = x[(size_t)mr * (DIMX * NC) + ir * NC + c];
    __syncthreads();
    const int iw = i0 + ty, mw = m0 + tx;
    #pragma unroll
    for (int c = 0; c < NC; c++)
        g_xt[(size_t)c * DIMX * MTOT + (size_t)iw * MTOT + mw] = s[c][tx][ty];
}

// ---------------- 2) transpose weights ----------------
__global__ void k_transpose_w(const float* __restrict__ wq,
                              const float* __restrict__ wkv,
                              const float* __restrict__ wout) {
    const int idx = blockIdx.x * 256 + threadIdx.x;
    if (idx < DIMX * OALL) {
        const int i = idx / OALL, o = idx % OALL;
        g_wt_all[idx] = (o < DI) ? wq[(size_t)o * DIMX + i]
                                 : wkv[(size_t)(o - DI) * DIMX + i];
    }
    if (idx < DI * DIMX) {
        const int i = idx / DIMX, o = idx % DIMX;
        g_wt_out[idx] = wout[(size_t)o * DI + i];
    }
}

// ---------------- 3) QKV projection SGEMM (f32x2) ----------------
__global__ void k_gemm_proj() {
    __shared__ float As[32][64];
    __shared__ float Bs[32][64];
    const int c  = blockIdx.z;
    const int m0 = blockIdx.x * 64;
    const int o0 = blockIdx.y * 64;
    const float* A = g_xt + (size_t)c * DIMX * MTOT;
    const int t = threadIdx.x;
    const int tm = t & 15, tn = t >> 4;

    u64 ap[4][2];
    #pragma unroll
    for (int a = 0; a < 4; a++) { ap[a][0] = 0ull; ap[a][1] = 0ull; }

    for (int k0 = 0; k0 < DIMX; k0 += 32) {
        #pragma unroll
        for (int j = 0; j < 2; j++) {
            const int p = t + j * 256;
            const int kk = p >> 4, x4 = (p & 15) << 2;
            *(float4*)&As[kk][x4] = *(const float4*)&A[(size_t)(k0 + kk) * MTOT + m0 + x4];
            *(float4*)&Bs[kk][x4] = *(const float4*)&g_wt_all[(size_t)(k0 + kk) * OALL + o0 + x4];
        }
        __syncthreads();
        #pragma unroll
        for (int k = 0; k < 32; k++) {
            const ulonglong2 rbp = *(const ulonglong2*)&Bs[k][tn << 2];
            #pragma unroll
            for (int im = 0; im < 4; im++) {
                const u64 rad = pk2(As[k][tm + im * 16]);
                fma2(ap[im][0], rad, rbp.x);
                fma2(ap[im][1], rad, rbp.y);
            }
        }
        __syncthreads();
    }

    #pragma unroll
    for (int im = 0; im < 4; im++) {
        const int m = m0 + tm + im * 16;
        const int b = m >> 11, n = m & 2047;
        const float2 e0 = up2(ap[im][0]);
        const float2 e1 = up2(ap[im][1]);
        float vals[4] = {e0.x, e0.y, e1.x, e1.y};
        #pragma unroll
        for (int io = 0; io < 4; io++) {
            const int o = o0 + (tn << 2) + io;
            const float v = vals[io];
            if (o < 2 * DI) {
                const int oo = o & 511;
                const int h = oo >> 6, d = oo & 63;
                float* dst = (o < DI) ? g_Qt : g_Kt;
                dst[((size_t)(b * NH + h) * FF + c * DHD + d) * N_ + n] = v;
            } else {
                const int oo = o - 2 * DI;
                const int h = oo >> 6, d = oo & 63;
                g_Vn[((size_t)(b * NH + h) * N_ + n) * FF + c * DHD + d] = v;
            }
        }
    }
}

// ---------------- 4) k_sq ----------------
__global__ void k_ksq() {
    const int bh = blockIdx.y;
    const int n  = blockIdx.x * 256 + threadIdx.x;
    const float* kp = g_Kt + (size_t)bh * FF * N_ + n;
    float s = 0.f;
    #pragma unroll 4
    for (int f = 0; f < FF; f++) {
        const float v = kp[(size_t)f * N_];
        s = fmaf(v, v, s);
    }
    g_ksq[bh * N_ + n] = s;
}

// ---------------- 5) attention (f32x2, split-KV) ----------------
// block = (q-tile 64, bh, split). 8 warps x 8 query rows.
// S-phase: accumulator pairs over adjacent q rows. PV: pairs over adjacent f.
__global__ void __launch_bounds__(256, 1) k_attn() {
    extern __shared__ float sm[];
    float* sQ = sm;                    // [192][64]
    float* sK = sQ + FF * 64;          // [192][64]
    float* sV = sK + FF * 64;          // [64][192]
    float* sP = sV + 64 * FF;          // [8 warps][8 qi][64 kj]
    float* sB = sP + 8 * 8 * 64;       // [64]

    const int bh = blockIdx.y;
    const int q0 = blockIdx.x * 64;
    const int z  = blockIdx.z;
    const int b  = bh >> 3;
    const int t  = threadIdx.x;
    const int w  = t >> 5, l = t & 31;
    const int qb = w * 8;

    const float* Qg = g_Qt + (size_t)bh * FF * N_;
    const float* Kg = g_Kt + (size_t)bh * FF * N_;
    const float* Vg = g_Vn + (size_t)bh * N_ * FF;
    const float* kqg = g_ksq + bh * N_;
    const unsigned char* mg = g_mask + b * N_;

    #pragma unroll
    for (int j = 0; j < 12; j++) {
        const int p = t + j * 256;
        const int f = p >> 4, x4 = (p & 15) << 2;
        *(float4*)&sQ[f * 64 + x4] = *(const float4*)&Qg[(size_t)f * N_ + q0 + x4];
    }

    float m_r[8], l_r[8];
    u64 op[8][3];
    #pragma unroll
    for (int i = 0; i < 8; i++) {
        m_r[i] = NEG_BIG; l_r[i] = 0.f;
        op[i][0] = 0ull; op[i][1] = 0ull; op[i][2] = 0ull;
    }

    float* pw = sP + w * 512;
    const int kbeg = z * KRANGE;

    for (int kt = kbeg; kt < kbeg + KRANGE; kt += 64) {
        __syncthreads();
        #pragma unroll
        for (int j = 0; j < 12; j++) {
            const int p = t + j * 256;
            const int f = p >> 4, x4 = (p & 15) << 2;
            *(float4*)&sK[f * 64 + x4] = *(const float4*)&Kg[(size_t)f * N_ + kt + x4];
        }
        #pragma unroll
        for (int j = 0; j < 12; j++) {
            const int p = t + j * 256;
            const int r = p / 48, f4 = (p % 48) << 2;
            *(float4*)&sV[r * FF + f4] = *(const float4*)&Vg[(size_t)(kt + r) * FF + f4];
        }
        if (t < 64) {
            const int jj = kt + t;
            sB[t] = mg[jj] ? -kqg[jj] : NEG_BIG;
        }
        __syncthreads();

        // ---- S = Q.K^T : pairs over q rows; lane owns kj = 2l, 2l+1 ----
        u64 sp[4][2];
        #pragma unroll
        for (int pp = 0; pp < 4; pp++) { sp[pp][0] = 0ull; sp[pp][1] = 0ull; }
        #pragma unroll 4
        for (int f = 0; f < FF; f++) {
            const ulonglong2 qA = *(const ulonglong2*)&sQ[f * 64 + qb];      // (q0,q1),(q2,q3)
            const ulonglong2 qB = *(const ulonglong2*)&sQ[f * 64 + qb + 4];  // (q4,q5),(q6,q7)
            const float2 kk = *(const float2*)&sK[f * 64 + 2 * l];
            const u64 k0 = pk2(kk.x);
            const u64 k1 = pk2(kk.y);
            fma2(sp[0][0], qA.x, k0); fma2(sp[0][1], qA.x, k1);
            fma2(sp[1][0], qA.y, k0); fma2(sp[1][1], qA.y, k1);
            fma2(sp[2][0], qB.x, k0); fma2(sp[2][1], qB.x, k1);
            fma2(sp[3][0], qB.y, k0); fma2(sp[3][1], qB.y, k1);
        }

        // unpack to scalars
        float s0[8], s1[8];
        #pragma unroll
        for (int pp = 0; pp < 4; pp++) {
            const float2 a = up2(sp[pp][0]);   // (row 2pp, row 2pp+1) @ kj=2l
            const float2 bb = up2(sp[pp][1]);  // @ kj=2l+1
            s0[2 * pp] = a.x;  s0[2 * pp + 1] = a.y;
            s1[2 * pp] = bb.x; s1[2 * pp + 1] = bb.y;
        }

        const float bb0 = sB[2 * l], bb1 = sB[2 * l + 1];
        #pragma unroll
        for (int i = 0; i < 8; i++) {
            s0[i] = (2.f * s0[i] + bb0) * SCALE_F;
            s1[i] = (2.f * s1[i] + bb1) * SCALE_F;
        }

        float mt[8];
        #pragma unroll
        for (int i = 0; i < 8; i++) mt[i] = fmaxf(s0[i], s1[i]);
        #pragma unroll
        for (int off = 16; off; off >>= 1)
            #pragma unroll
            for (int i = 0; i < 8; i++)
                mt[i] = fmaxf(mt[i], __shfl_xor_sync(0xffffffffu, mt[i], off));

        float rs[8];
        #pragma unroll
        for (int i = 0; i < 8; i++) {
            const float mn = fmaxf(m_r[i], mt[i]);
            const float al = __expf(m_r[i] - mn);
            m_r[i] = mn;
            s0[i] = __expf(s0[i] - mn);
            s1[i] = __expf(s1[i] - mn);
            rs[i] = s0[i] + s1[i];
            l_r[i] *= al;
            const u64 ald = pk2(al);
            op[i][0] = mul2(op[i][0], ald);
            op[i][1] = mul2(op[i][1], ald);
            op[i][2] = mul2(op[i][2], ald);
        }
        #pragma unroll
        for (int off = 16; off; off >>= 1)
            #pragma unroll
            for (int i = 0; i < 8; i++)
                rs[i] += __shfl_xor_sync(0xffffffffu, rs[i], off);
        #pragma unroll
        for (int i = 0; i < 8; i++) l_r[i] += rs[i];

        #pragma unroll
        for (int i = 0; i < 8; i++) {
            float2 pp; pp.x = s0[i]; pp.y = s1[i];
            *(float2*)&pw[i * 64 + 2 * l] = pp;
        }
        __syncwarp();

        // ---- O += P.V : pairs over f; lane owns f-pairs (2l,2l+1)+{0,64,128} ----
        #pragma unroll 2
        for (int kj = 0; kj < 64; kj++) {
            const u64 v0 = *(const u64*)&sV[kj * FF + 2 * l];
            const u64 v1 = *(const u64*)&sV[kj * FF + 64 + 2 * l];
            const u64 v2 = *(const u64*)&sV[kj * FF + 128 + 2 * l];
            #pragma unroll
            for (int i = 0; i < 8; i++) {
                const u64 pd = pk2(pw[i * 64 + kj]);
                fma2(op[i][0], pd, v0);
                fma2(op[i][1], pd, v1);
                fma2(op[i][2], pd, v2);
            }
        }
        __syncwarp();
    }

    // epilogue: store UNNORMALIZED partial O + (m, l)
    float* pO = g_pO + ((size_t)(z * BHCNT + bh) * N_) * FF;
    #pragma unroll
    for (int i = 0; i < 8; i++) {
        const size_t base = (size_t)(q0 + qb + i) * FF;
        *(u64*)&pO[base + 2 * l]       = op[i][0];
        *(u64*)&pO[base + 64 + 2 * l]  = op[i][1];
        *(u64*)&pO[base + 128 + 2 * l] = op[i][2];
    }
    if (l == 0) {
        const size_t rb = (size_t)(z * BHCNT + bh) * N_ + q0 + qb;
        #pragma unroll
        for (int i = 0; i < 8; i++) {
            g_pm[rb + i] = m_r[i];
            g_pl[rb + i] = l_r[i];
        }
    }
}

// ---------------- 5b) split-KV combine -> g_Oct[c][i][m] ----------------
__global__ void __launch_bounds__(256) k_combine() {
    extern __shared__ float smc[];
    float* sO = smc;                        // [192][68] (f-major, padded)
    __shared__ float w0s[64], w1s[64];

    const int bh = blockIdx.y;
    const int q0 = blockIdx.x * 64;
    const int b  = bh >> 3;
    const int h  = bh & 7;
    const int t  = threadIdx.x;

    if (t < 64) {
        const size_t r0 = (size_t)(0 * BHCNT + bh) * N_ + q0 + t;
        const size_t r1 = (size_t)(1 * BHCNT + bh) * N_ + q0 + t;
        const float m0 = g_pm[r0], m1 = g_pm[r1];
        const float M = fmaxf(m0, m1);
        const float e0 = __expf(m0 - M), e1 = __expf(m1 - M);
        const float L = g_pl[r0] * e0 + g_pl[r1] * e1;
        const float inv = 1.f / L;
        w0s[t] = e0 * inv;
        w1s[t] = e1 * inv;
    }
    __syncthreads();

    const float* p0 = g_pO + ((size_t)(0 * BHCNT + bh) * N_ + q0) * FF;
    const float* p1 = g_pO + ((size_t)(1 * BHCNT + bh) * N_ + q0) * FF;
    #pragma unroll
    for (int j = 0; j < 48; j++) {
        const int idx = t + j * 256;        // over 64*192
        const int q = idx / FF, f = idx % FF;
        sO[f * 68 + q] = w0s[q] * p0[(size_t)q * FF + f] + w1s[q] * p1[(size_t)q * FF + f];
    }
    __syncthreads();

    #pragma unroll
    for (int j = 0; j < 12; j++) {
        const int u = t + j * 256;          // over 192*16 float4s
        const int f = u >> 4, q4 = (u & 15) << 2;
        const int cc = f >> 6, d = f & 63;
        const float4 v = *(const float4*)&sO[f * 68 + q4];
        *(float4*)&g_Oct[(size_t)cc * DI * MTOT + (size_t)(h * DHD + d) * MTOT
                         + b * N_ + q0 + q4] = v;
    }
}

// ---------------- 6) output projection SGEMM (f32x2) ----------------
__global__ void k_gemm_out(float* __restrict__ out) {
    __shared__ float As[32][64];
    __shared__ float Bs[32][64];
    const int c  = blockIdx.z;
    const int m0 = blockIdx.x * 64;
    const int o0 = blockIdx.y * 64;
    const float* A = g_Oct + (size_t)c * DI * MTOT;
    const int t = threadIdx.x;
    const int tm = t & 15, tn = t >> 4;

    u64 ap[4][2];
    #pragma unroll
    for (int a = 0; a < 4; a++) { ap[a][0] = 0ull; ap[a][1] = 0ull; }

    for (int k0 = 0; k0 < DI; k0 += 32) {
        #pragma unroll
        for (int j = 0; j < 2; j++) {
            const int p = t + j * 256;
            const int kk = p >> 4, x4 = (p & 15) << 2;
            *(float4*)&As[kk][x4] = *(const float4*)&A[(size_t)(k0 + kk) * MTOT + m0 + x4];
            *(float4*)&Bs[kk][x4] = *(const float4*)&g_wt_out[(size_t)(k0 + kk) * DIMX + o0 + x4];
        }
        __syncthreads();
        #pragma unroll
        for (int k = 0; k < 32; k++) {
            const ulonglong2 rbp = *(const ulonglong2*)&Bs[k][tn << 2];
            #pragma unroll
            for (int im = 0; im < 4; im++) {
                const u64 rad = pk2(As[k][tm + im * 16]);
                fma2(ap[im][0], rad, rbp.x);
                fma2(ap[im][1], rad, rbp.y);
            }
        }
        __syncthreads();
    }

    #pragma unroll
    for (int im = 0; im < 4; im++) {
        const int m = m0 + tm + im * 16;
        const float2 e0 = up2(ap[im][0]);
        const float2 e1 = up2(ap[im][1]);
        float vals[4] = {e0.x, e0.y, e1.x, e1.y};
        #pragma unroll
        for (int io = 0; io < 4; io++) {
            const int o = o0 + (tn << 2) + io;
            out[(size_t)m * (DIMX * NC) + o * NC + c] = vals[io];
        }
    }
}

// ---------------- launch ----------------
extern "C" void kernel_launch(void* const* d_in, const int* in_sizes, int n_in,
                              void* d_out, int out_size) {
    (void)in_sizes; (void)n_in; (void)out_size;
    const float* x    = (const float*)d_in[0];
    const void*  mask = d_in[1];
    const float* wq   = (const float*)d_in[2];
    const float* wkv  = (const float*)d_in[3];
    const float* wout = (const float*)d_in[4];
    float* out = (float*)d_out;

    const size_t ATTN_SMEM =
        (size_t)(FF * 64 * 2 + 64 * FF + 8 * 8 * 64 + 64) * sizeof(float); // 164096 B
    const size_t COMB_SMEM = (size_t)(FF * 68) * sizeof(float);            // 52224 B
    cudaFuncSetAttribute(k_attn, cudaFuncAttributeMaxDynamicSharedMemorySize,
                         (int)ATTN_SMEM);
    cudaFuncSetAttribute(k_combine, cudaFuncAttributeMaxDynamicSharedMemorySize,
                         (int)COMB_SMEM);

    k_mask_prep<<<dim3((MTOT + 255) / 256), 256>>>(mask);
    k_transpose_x<<<dim3(DIMX / 32, MTOT / 32), dim3(32, 32)>>>(x);
    k_transpose_w<<<dim3((DIMX * OALL + 255) / 256), 256>>>(wq, wkv, wout);
    k_gemm_proj<<<dim3(MTOT / 64, OALL / 64, NC), 256>>>();
    k_ksq<<<dim3(N_ / 256, BHCNT), 256>>>();
    k_attn<<<dim3(N_ / 64, BHCNT, KSPLIT), 256, ATTN_SMEM>>>();
    k_combine<<<dim3(N_ / 64, BHCNT), 256, COMB_SMEM>>>();
    k_gemm_out<<<dim3(MTOT / 64, DIMX / 64, NC), 256>>>(out);
}